// round 11
// baseline (speedup 1.0000x reference)
#include <cuda_runtime.h>
#include <cuda_fp16.h>

#define N_NODES 50000
#define N_EDGES 800000
#define E2      850000   // edges + self loops
#define IN_F    128
#define HID     64
#define BN_EPS  1e-5f
#define INV_Nf  (1.0f / 50000.0f)

// ---------------- scratch (device globals; no allocation allowed) ----------------
__device__ int    g_is64;
__device__ int    g_deg[N_NODES];
__device__ int    g_fill[N_NODES];
__device__ float  g_dinv[N_NODES];
__device__ int    g_rowptr[N_NODES + 1];
__device__ __align__(16) int2 g_cw[E2 + 4];  // {col, weight-bits}; padded for int4 tail
__device__ __half g_hA[N_NODES * HID];
__device__ __half g_hB[N_NODES * HID];
__device__ __half g_h0[N_NODES * HID];
__device__ float  g_sumf[4][HID];
__device__ float  g_sqf[4][HID];

// ---------------- init: deg=1, fill=0, zero stats, detect edge dtype ----------------
__global__ void init_kernel(const int* __restrict__ e) {
    int n = blockIdx.x * blockDim.x + threadIdx.x;
    if (n < N_NODES) { g_deg[n] = 1; g_fill[n] = 0; }
    if (blockIdx.x == 0) {
        int t = threadIdx.x;
        if (t < 4 * HID) { ((float*)g_sumf)[t] = 0.f; ((float*)g_sqf)[t] = 0.f; }
        if (t < 32) {
            // int64 little-endian with values < 50000 -> odd 32-bit words all zero
            int nz = 0;
            #pragma unroll
            for (int i = 0; i < 4; i++) nz += (e[2 * (t * 4 + i) + 1] != 0);
            unsigned any = __any_sync(0xffffffffu, nz != 0);
            if (t == 0) g_is64 = any ? 0 : 1;
        }
    }
}

__device__ __forceinline__ int fetch_idx(const void* ei, long long pos) {
    int v;
    if (g_is64) v = (int)((const long long*)ei)[pos];
    else        v = ((const int*)ei)[pos];
    return min(max(v, 0), N_NODES - 1);   // crash insurance
}

__global__ void count_deg_kernel(const void* __restrict__ ei) {
    int e = blockIdx.x * blockDim.x + threadIdx.x;
    if (e < N_EDGES) atomicAdd(&g_deg[fetch_idx(ei, (long long)N_EDGES + e)], 1);
}

// single-block COALESCED scan: 32 warps, lane-strided loads, shfl scans; also writes dinv
__global__ void scan_kernel() {
    __shared__ int wsum[32], woff[32];
    const int REG = (N_NODES + 31) / 32;     // 1563 per warp region
    int wid  = threadIdx.x >> 5;
    int lane = threadIdx.x & 31;
    int base = wid * REG;
    // pass 1: region totals (coalesced) + dinv
    int tot = 0;
    for (int i = 0; i < REG; i += 32) {
        int off = i + lane;
        int idx = base + off;
        int d = 0;
        if (off < REG && idx < N_NODES) {
            d = g_deg[idx];
            g_dinv[idx] = rsqrtf((float)d);
        }
        tot += d;
    }
    for (int o = 16; o; o >>= 1) tot += __shfl_xor_sync(0xffffffffu, tot, o);
    if (lane == 0) wsum[wid] = tot;
    __syncthreads();
    if (threadIdx.x < 32) {
        int v  = wsum[threadIdx.x];
        int ex = v;
        for (int o = 1; o < 32; o <<= 1) {
            int nb = __shfl_up_sync(0xffffffffu, ex, o);
            if (lane >= o) ex += nb;
        }
        woff[threadIdx.x] = ex - v;           // exclusive region offset
        if (threadIdx.x == 31) g_rowptr[N_NODES] = ex;
    }
    __syncthreads();
    // pass 2: ordered exclusive scan within region (coalesced rows of 32)
    int run = woff[wid];
    for (int i = 0; i < REG; i += 32) {
        int off = i + lane;
        int idx = base + off;
        bool ok = (off < REG) && (idx < N_NODES);
        int d = ok ? g_deg[idx] : 0;
        int ex = d;
        for (int o = 1; o < 32; o <<= 1) {
            int nb = __shfl_up_sync(0xffffffffu, ex, o);
            if (lane >= o) ex += nb;
        }
        int rowtot = __shfl_sync(0xffffffffu, ex, 31);
        ex -= d;                               // exclusive within row
        if (ok) g_rowptr[idx] = run + ex;
        run += rowtot;
    }
}

__global__ void fill_csr_kernel(const void* __restrict__ ei) {
    int e = blockIdx.x * blockDim.x + threadIdx.x;
    if (e >= E2) return;
    int s, d;
    if (e < N_EDGES) {
        s = fetch_idx(ei, e);
        d = fetch_idx(ei, (long long)N_EDGES + e);
    } else {
        s = e - N_EDGES; d = s;
    }
    int pos = g_rowptr[d] + atomicAdd(&g_fill[d], 1);
    g_cw[pos] = make_int2(s, __float_as_int(g_dinv[s] * g_dinv[d]));
}

__device__ __forceinline__ float4 cvt8(uint2 u) {
    float2 a = __half22float2(*reinterpret_cast<__half2*>(&u.x));
    float2 b = __half22float2(*reinterpret_cast<__half2*>(&u.y));
    return make_float4(a.x, a.y, b.x, b.y);
}

// ---------------- SpMM (fp16 h): warp per node, PAIRED edges ----------------
// 16-lane halves: one LDG.64 gathers TWO edge rows (sub=0 -> even edge, sub=1 -> odd).
// Halves merged by shfl_xor(16); low half applies bias/h0 and stores (64B, coalesced).
template <bool STATS>
__global__ __launch_bounds__(256) void spmm_kernel(
    const __half* __restrict__ hin, __half* __restrict__ hout,
    const float* __restrict__ bias, const __half* __restrict__ h0p,
    float wacc, float wh0, int set)
{
    __shared__ float ss[STATS ? 8 : 1][STATS ? HID : 1];
    __shared__ float qq[STATS ? 8 : 1][STATS ? HID : 1];
    int warp = threadIdx.x >> 5;
    int node = blockIdx.x * 8 + warp;
    int lane = threadIdx.x & 31;
    int sub  = lane >> 4;        // which edge of the pair
    int fl   = lane & 15;        // 8-byte chunk within the 128B row
    const uint2* __restrict__ hin4 = (const uint2*)hin;
    const int4*  __restrict__ cw4  = (const int4*)g_cw;
    int beg = g_rowptr[node];
    int end = g_rowptr[node + 1];
    float4 a0 = make_float4(0.f, 0.f, 0.f, 0.f), a1 = a0, a2 = a0, a3 = a0;
    int e = beg;
    if ((e & 1) && e < end) {            // peel to even index for int4 metadata
        int2 cw = g_cw[e];
        float w = sub ? 0.f : __int_as_float(cw.y);
        float4 v = cvt8(hin4[cw.x * 16 + fl]);
        a0.x += w*v.x; a0.y += w*v.y; a0.z += w*v.z; a0.w += w*v.w;
        e++;
    }
    for (; e + 7 < end; e += 8) {        // 8 edges = 4 paired gathers
        int4 q0 = cw4[e >> 1];
        int4 q1 = cw4[(e >> 1) + 1];
        int4 q2 = cw4[(e >> 1) + 2];
        int4 q3 = cw4[(e >> 1) + 3];
        int   c0 = sub ? q0.z : q0.x;  float w0 = __int_as_float(sub ? q0.w : q0.y);
        int   c1 = sub ? q1.z : q1.x;  float w1 = __int_as_float(sub ? q1.w : q1.y);
        int   c2 = sub ? q2.z : q2.x;  float w2 = __int_as_float(sub ? q2.w : q2.y);
        int   c3 = sub ? q3.z : q3.x;  float w3 = __int_as_float(sub ? q3.w : q3.y);
        float4 v0 = cvt8(hin4[c0*16 + fl]);
        float4 v1 = cvt8(hin4[c1*16 + fl]);
        float4 v2 = cvt8(hin4[c2*16 + fl]);
        float4 v3 = cvt8(hin4[c3*16 + fl]);
        a0.x += w0*v0.x; a0.y += w0*v0.y; a0.z += w0*v0.z; a0.w += w0*v0.w;
        a1.x += w1*v1.x; a1.y += w1*v1.y; a1.z += w1*v1.z; a1.w += w1*v1.w;
        a2.x += w2*v2.x; a2.y += w2*v2.y; a2.z += w2*v2.z; a2.w += w2*v2.w;
        a3.x += w3*v3.x; a3.y += w3*v3.y; a3.z += w3*v3.z; a3.w += w3*v3.w;
    }
    for (; e + 1 < end; e += 2) {        // paired tail
        int4 q = cw4[e >> 1];
        int c = sub ? q.z : q.x;  float w = __int_as_float(sub ? q.w : q.y);
        float4 v = cvt8(hin4[c*16 + fl]);
        a0.x += w*v.x; a0.y += w*v.y; a0.z += w*v.z; a0.w += w*v.w;
    }
    if (e < end) {                        // single leftover edge
        int2 cw = g_cw[e];
        float w = sub ? 0.f : __int_as_float(cw.y);
        float4 v = cvt8(hin4[cw.x * 16 + fl]);
        a0.x += w*v.x; a0.y += w*v.y; a0.z += w*v.z; a0.w += w*v.w;
    }
    float4 A;
    A.x = (a0.x + a1.x) + (a2.x + a3.x);
    A.y = (a0.y + a1.y) + (a2.y + a3.y);
    A.z = (a0.z + a1.z) + (a2.z + a3.z);
    A.w = (a0.w + a1.w) + (a2.w + a3.w);
    A.x += __shfl_xor_sync(0xffffffffu, A.x, 16);
    A.y += __shfl_xor_sync(0xffffffffu, A.y, 16);
    A.z += __shfl_xor_sync(0xffffffffu, A.z, 16);
    A.w += __shfl_xor_sync(0xffffffffu, A.w, 16);
    if (sub == 0) {
        float4 r = make_float4(A.x * wacc, A.y * wacc, A.z * wacc, A.w * wacc);
        if (bias) {
            float4 b = ((const float4*)bias)[fl];
            r.x += b.x; r.y += b.y; r.z += b.z; r.w += b.w;
        }
        if (h0p) {
            float4 z = cvt8(((const uint2*)h0p)[node * 16 + fl]);
            r.x += wh0 * z.x; r.y += wh0 * z.y; r.z += wh0 * z.z; r.w += wh0 * z.w;
        }
        __half2 o0 = __floats2half2_rn(r.x, r.y);
        __half2 o1 = __floats2half2_rn(r.z, r.w);
        uint2 o;
        o.x = *reinterpret_cast<unsigned*>(&o0);
        o.y = *reinterpret_cast<unsigned*>(&o1);
        ((uint2*)hout)[node * 16 + fl] = o;
        if (STATS) {
            ss[warp][fl*4 + 0] = r.x; ss[warp][fl*4 + 1] = r.y;
            ss[warp][fl*4 + 2] = r.z; ss[warp][fl*4 + 3] = r.w;
            qq[warp][fl*4 + 0] = r.x*r.x; qq[warp][fl*4 + 1] = r.y*r.y;
            qq[warp][fl*4 + 2] = r.z*r.z; qq[warp][fl*4 + 3] = r.w*r.w;
        }
    }
    if (STATS) {
        __syncthreads();
        int t = threadIdx.x;
        if (t < HID) {
            float s = 0.f;
#pragma unroll
            for (int g = 0; g < 8; g++) s += ss[g][t];
            atomicAdd(&g_sumf[set][t], s);
        } else if (t < 2 * HID) {
            float q = 0.f;
#pragma unroll
            for (int g = 0; g < 8; g++) q += qq[g][t - HID];
            atomicAdd(&g_sqf[set][t - HID], q);
        }
    }
}

// ---------------- dense GEMM, retiled: block = 128 nodes x 64 features ----------------
// thread tile = 4 nodes x 8 features; K chunked by 32; fused BN(+ReLU) on input when BNSET>=0
template <int KIN, int BNSET, typename TA>
__global__ __launch_bounds__(256) void gemm_kernel(
    const TA* __restrict__ A, const float* __restrict__ W,
    const float* __restrict__ bias, __half* __restrict__ C,
    const float* __restrict__ gam, const float* __restrict__ bet)
{
    __shared__ float As[128][33];        // K-chunk: 128 nodes x 32 k (padded)
    __shared__ float Ws[32][64];         // K-chunk: 32 k x 64 features
    __shared__ float sc[HID], sh[HID];
    int tid = threadIdx.x;
    if (BNSET >= 0) {
        if (tid < HID) {
            float mean = g_sumf[BNSET][tid] * INV_Nf;
            float var  = g_sqf[BNSET][tid] * INV_Nf - mean * mean;
            float s = gam[tid] * rsqrtf(var + BN_EPS);
            sc[tid] = s;
            sh[tid] = bet[tid] - mean * s;
        }
        __syncthreads();
    }
    int base = blockIdx.x * 128;
    int ftb  = (tid & 7) * 8;            // feature base (0..56)
    int ntb  = (tid >> 3) * 4;           // node base within block (0..124)
    float acc[4][8];
#pragma unroll
    for (int i = 0; i < 4; i++)
#pragma unroll
        for (int j = 0; j < 8; j++) acc[i][j] = 0.f;

    for (int k0 = 0; k0 < KIN; k0 += 32) {
        for (int i = tid; i < 128 * 16; i += 256) {
            int r = i >> 4, c = (i & 15) * 2;
            float v0 = 0.f, v1 = 0.f;
            if (base + r < N_NODES) {
                if constexpr (sizeof(TA) == 2) {
                    float2 p = __half22float2(((const __half2*)A)[((base + r) * KIN + k0 + c) >> 1]);
                    v0 = p.x; v1 = p.y;
                } else {
                    float2 p = ((const float2*)A)[((base + r) * KIN + k0 + c) >> 1];
                    v0 = p.x; v1 = p.y;
                }
            }
            if (BNSET >= 0) {
                v0 = fmaxf(fmaf(v0, sc[k0 + c],     sh[k0 + c]),     0.f);
                v1 = fmaxf(fmaf(v1, sc[k0 + c + 1], sh[k0 + c + 1]), 0.f);
            }
            As[r][c]     = v0;
            As[r][c + 1] = v1;
        }
        for (int i = tid; i < 32 * 64; i += 256) {
            int kk = i >> 6, f = i & 63;
            Ws[kk][f] = W[(k0 + kk) * 64 + f];
        }
        __syncthreads();
#pragma unroll 8
        for (int kk = 0; kk < 32; kk++) {
            float4 wa = *(const float4*)&Ws[kk][ftb];
            float4 wb = *(const float4*)&Ws[kk][ftb + 4];
            float a0 = As[ntb + 0][kk];
            float a1 = As[ntb + 1][kk];
            float a2 = As[ntb + 2][kk];
            float a3 = As[ntb + 3][kk];
            acc[0][0] += a0*wa.x; acc[0][1] += a0*wa.y; acc[0][2] += a0*wa.z; acc[0][3] += a0*wa.w;
            acc[0][4] += a0*wb.x; acc[0][5] += a0*wb.y; acc[0][6] += a0*wb.z; acc[0][7] += a0*wb.w;
            acc[1][0] += a1*wa.x; acc[1][1] += a1*wa.y; acc[1][2] += a1*wa.z; acc[1][3] += a1*wa.w;
            acc[1][4] += a1*wb.x; acc[1][5] += a1*wb.y; acc[1][6] += a1*wb.z; acc[1][7] += a1*wb.w;
            acc[2][0] += a2*wa.x; acc[2][1] += a2*wa.y; acc[2][2] += a2*wa.z; acc[2][3] += a2*wa.w;
            acc[2][4] += a2*wb.x; acc[2][5] += a2*wb.y; acc[2][6] += a2*wb.z; acc[2][7] += a2*wb.w;
            acc[3][0] += a3*wa.x; acc[3][1] += a3*wa.y; acc[3][2] += a3*wa.z; acc[3][3] += a3*wa.w;
            acc[3][4] += a3*wb.x; acc[3][5] += a3*wb.y; acc[3][6] += a3*wb.z; acc[3][7] += a3*wb.w;
        }
        __syncthreads();
    }
    float bv[8];
#pragma unroll
    for (int j = 0; j < 8; j++) bv[j] = bias ? bias[ftb + j] : 0.f;
#pragma unroll
    for (int i = 0; i < 4; i++) {
        int node = base + ntb + i;
        if (node < N_NODES) {
#pragma unroll
            for (int j = 0; j < 8; j += 2) {
                ((__half2*)C)[(node * 64 + ftb + j) >> 1] =
                    __floats2half2_rn(acc[i][j] + bv[j], acc[i][j + 1] + bv[j + 1]);
            }
        }
    }
}

// ---------------- layer-4 BN apply (inline finalize) -> writes h and h0 (fp16) ----------------
__global__ __launch_bounds__(256) void bn_apply_final_kernel(
    __half* __restrict__ h, __half* __restrict__ h0,
    const float* __restrict__ gam, const float* __restrict__ bet)
{
    __shared__ float sc[HID], sh[HID];
    int tid = threadIdx.x;
    if (tid < HID) {
        float mean = g_sumf[3][tid] * INV_Nf;
        float var  = g_sqf[3][tid] * INV_Nf - mean * mean;
        float s = gam[tid] * rsqrtf(var + BN_EPS);
        sc[tid] = s;
        sh[tid] = bet[tid] - mean * s;
    }
    __syncthreads();
    int i = blockIdx.x * blockDim.x + tid;   // over N*32 half2s (exact)
    float2 v = __half22float2(((const __half2*)h)[i]);
    int f = (i * 2) & (HID - 1);
    v.x = fmaxf(fmaf(v.x, sc[f],     sh[f]),     0.f);
    v.y = fmaxf(fmaf(v.y, sc[f + 1], sh[f + 1]), 0.f);
    __half2 o = __floats2half2_rn(v.x, v.y);
    ((__half2*)h)[i]  = o;
    ((__half2*)h0)[i] = o;
}

// ---------------- fused FC + log-softmax: out = log_softmax(A @ Wfc + bfc) ----------------
__global__ __launch_bounds__(256) void fc_logsoftmax_kernel(
    const __half* __restrict__ A, const float* __restrict__ W,
    const float* __restrict__ bias, float* __restrict__ out)
{
    __shared__ float Ws[64 * 64];
    __shared__ float As[32 * 64];
    __shared__ float L[32][65];
    int tid = threadIdx.x;
    for (int i = tid; i < 64 * 64; i += 256) Ws[i] = W[i];
    int base = blockIdx.x * 32;
    for (int i = tid; i < 32 * 32; i += 256) {     // 32 rows x 32 half2
        int r = i / 32, c = (i - r * 32) * 2;
        float2 p = make_float2(0.f, 0.f);
        if (base + r < N_NODES)
            p = __half22float2(((const __half2*)A)[((base + r) * 64 + c) >> 1]);
        As[r * 64 + c]     = p.x;
        As[r * 64 + c + 1] = p.y;
    }
    __syncthreads();
    int f  = tid & 63;
    int ig = tid >> 6;
    float acc[8];
#pragma unroll
    for (int i = 0; i < 8; i++) acc[i] = 0.f;
#pragma unroll 8
    for (int k = 0; k < 64; k++) {
        float wv = Ws[k * 64 + f];
#pragma unroll
        for (int i = 0; i < 8; i++)
            acc[i] += As[(ig * 8 + i) * 64 + k] * wv;
    }
    float bv = bias[f];
#pragma unroll
    for (int i = 0; i < 8; i++) L[ig * 8 + i][f] = acc[i] + bv;
    __syncthreads();
    int w = tid >> 5, lane = tid & 31;
#pragma unroll
    for (int j = 0; j < 4; j++) {
        int r = w * 4 + j;
        int node = base + r;
        if (node >= N_NODES) break;
        float v0 = L[r][lane], v1 = L[r][lane + 32];
        float m = fmaxf(v0, v1);
        for (int o = 16; o; o >>= 1) m = fmaxf(m, __shfl_xor_sync(0xffffffffu, m, o));
        float s = __expf(v0 - m) + __expf(v1 - m);
        for (int o = 16; o; o >>= 1) s += __shfl_xor_sync(0xffffffffu, s, o);
        float ls = m + __logf(s);
        out[node * 64 + lane]      = v0 - ls;
        out[node * 64 + lane + 32] = v1 - ls;
    }
}

// ---------------- host ----------------
extern "C" void kernel_launch(void* const* d_in, const int* in_sizes, int n_in,
                              void* d_out, int out_size) {
    const float* x   = (const float*)d_in[0];
    const void*  ei  = d_in[1];            // int32 or int64, detected on device
    const float* W1  = (const float*)d_in[2];
    const float* b1  = (const float*)d_in[3];
    const float* W2  = (const float*)d_in[4];
    const float* b2  = (const float*)d_in[5];
    const float* Wx  = (const float*)d_in[6];   // [2,64,64]
    const float* bx  = (const float*)d_in[7];   // [2,64]
    const float* g1  = (const float*)d_in[8];
    const float* be1 = (const float*)d_in[9];
    const float* g2  = (const float*)d_in[10];
    const float* be2 = (const float*)d_in[11];
    const float* g3  = (const float*)d_in[12];
    const float* be3 = (const float*)d_in[13];
    const float* Wfc = (const float*)d_in[14];
    const float* bfc = (const float*)d_in[15];
    float* out = (float*)d_out;

    __half *hA, *hB, *h0;
    cudaGetSymbolAddress((void**)&hA, g_hA);
    cudaGetSymbolAddress((void**)&hB, g_hB);
    cudaGetSymbolAddress((void**)&h0, g_h0);

    // ---- build normalized CSR (by dst) ----
    init_kernel<<<(N_NODES + 255) / 256, 256>>>((const int*)ei);
    count_deg_kernel<<<(N_EDGES + 255) / 256, 256>>>(ei);
    scan_kernel<<<1, 1024>>>();
    fill_csr_kernel<<<(E2 + 255) / 256, 256>>>(ei);

    const int GEMM_GRID = (N_NODES + 127) / 128;   // 391
    const int FC_GRID   = (N_NODES + 31) / 32;     // 1563
    const int SPMM_GRID = N_NODES / 8;             // 6250

    // ---- layer 1 (IN_F=128 fp32 input, no BN) ----
    gemm_kernel<128, -1, float><<<GEMM_GRID, 256>>>(x, W1, nullptr, hB, nullptr, nullptr);
    spmm_kernel<true><<<SPMM_GRID, 256>>>(hB, hA, b1, nullptr, 1.f, 0.f, 0);
    // ---- layer 2 (BN set 0 fused into GEMM input) ----
    gemm_kernel<64, 0, __half><<<GEMM_GRID, 256>>>(hA, W2, nullptr, hB, g1, be1);
    spmm_kernel<true><<<SPMM_GRID, 256>>>(hB, hA, b2, nullptr, 1.f, 0.f, 1);
    // ---- extra layer 0 (BN set 1) ----
    gemm_kernel<64, 1, __half><<<GEMM_GRID, 256>>>(hA, Wx, nullptr, hB, g2, be2);
    spmm_kernel<true><<<SPMM_GRID, 256>>>(hB, hA, bx, nullptr, 1.f, 0.f, 2);
    // ---- extra layer 1 (BN set 2) ----
    gemm_kernel<64, 2, __half><<<GEMM_GRID, 256>>>(hA, Wx + 64 * 64, nullptr, hB, g3, be3);
    spmm_kernel<true><<<SPMM_GRID, 256>>>(hB, hA, bx + 64, nullptr, 1.f, 0.f, 3);
    // ---- final BN apply (set 3) -> hA normalized, h0 copy ----
    bn_apply_final_kernel<<<(N_NODES * 32) / 256, 256>>>(hA, h0, g3, be3);

    // ---- APPNP: 10 steps, ping-pong hA <-> hB ----
    __half* cur = hA;
    __half* nxt = hB;
    for (int it = 0; it < 10; it++) {
        spmm_kernel<false><<<SPMM_GRID, 256>>>(cur, nxt, nullptr, h0, 0.9f, 0.1f, 0);
        __half* t = cur; cur = nxt; nxt = t;
    }
    // result in hA

    // ---- head: FC + log_softmax fused ----
    fc_logsoftmax_kernel<<<FC_GRID, 256>>>(cur, Wfc, bfc, out);
}

// round 12
// speedup vs baseline: 1.2440x; 1.2440x over previous
#include <cuda_runtime.h>
#include <cuda_fp16.h>
#include <mma.h>

using namespace nvcuda;

#define N_NODES 50000
#define N_EDGES 800000
#define E2      850000   // edges + self loops
#define IN_F    128
#define HID     64
#define BN_EPS  1e-5f
#define INV_Nf  (1.0f / 50000.0f)

// ---------------- scratch (device globals; no allocation allowed) ----------------
__device__ int    g_is64;
__device__ int    g_deg[N_NODES];
__device__ int    g_fill[N_NODES];
__device__ float  g_dinv[N_NODES];
__device__ int    g_rowptr[N_NODES + 1];
__device__ __align__(16) int2 g_cw[E2 + 4];  // {col, weight-bits}; padded for int4 tail
__device__ __half g_hA[N_NODES * HID];
__device__ __half g_hB[N_NODES * HID];
__device__ __half g_h0[N_NODES * HID];
__device__ float  g_sumf[4][HID];
__device__ float  g_sqf[4][HID];

// ---------------- init: deg=1, fill=0, zero stats, detect edge dtype ----------------
__global__ void init_kernel(const int* __restrict__ e) {
    int n = blockIdx.x * blockDim.x + threadIdx.x;
    if (n < N_NODES) { g_deg[n] = 1; g_fill[n] = 0; }
    if (blockIdx.x == 0) {
        int t = threadIdx.x;
        if (t < 4 * HID) { ((float*)g_sumf)[t] = 0.f; ((float*)g_sqf)[t] = 0.f; }
        if (t < 32) {
            // int64 little-endian with values < 50000 -> odd 32-bit words all zero
            int nz = 0;
            #pragma unroll
            for (int i = 0; i < 4; i++) nz += (e[2 * (t * 4 + i) + 1] != 0);
            unsigned any = __any_sync(0xffffffffu, nz != 0);
            if (t == 0) g_is64 = any ? 0 : 1;
        }
    }
}

__device__ __forceinline__ int fetch_idx(const void* ei, long long pos) {
    int v;
    if (g_is64) v = (int)((const long long*)ei)[pos];
    else        v = ((const int*)ei)[pos];
    return min(max(v, 0), N_NODES - 1);   // crash insurance
}

__global__ void count_deg_kernel(const void* __restrict__ ei) {
    int e = blockIdx.x * blockDim.x + threadIdx.x;
    if (e < N_EDGES) atomicAdd(&g_deg[fetch_idx(ei, (long long)N_EDGES + e)], 1);
}

// single-block COALESCED scan: 32 warps, lane-strided loads, shfl scans; also writes dinv
__global__ void scan_kernel() {
    __shared__ int wsum[32], woff[32];
    const int REG = (N_NODES + 31) / 32;     // 1563 per warp region
    int wid  = threadIdx.x >> 5;
    int lane = threadIdx.x & 31;
    int base = wid * REG;
    int tot = 0;
    for (int i = 0; i < REG; i += 32) {
        int off = i + lane;
        int idx = base + off;
        int d = 0;
        if (off < REG && idx < N_NODES) {
            d = g_deg[idx];
            g_dinv[idx] = rsqrtf((float)d);
        }
        tot += d;
    }
    for (int o = 16; o; o >>= 1) tot += __shfl_xor_sync(0xffffffffu, tot, o);
    if (lane == 0) wsum[wid] = tot;
    __syncthreads();
    if (threadIdx.x < 32) {
        int v  = wsum[threadIdx.x];
        int ex = v;
        for (int o = 1; o < 32; o <<= 1) {
            int nb = __shfl_up_sync(0xffffffffu, ex, o);
            if (lane >= o) ex += nb;
        }
        woff[threadIdx.x] = ex - v;           // exclusive region offset
        if (threadIdx.x == 31) g_rowptr[N_NODES] = ex;
    }
    __syncthreads();
    int run = woff[wid];
    for (int i = 0; i < REG; i += 32) {
        int off = i + lane;
        int idx = base + off;
        bool ok = (off < REG) && (idx < N_NODES);
        int d = ok ? g_deg[idx] : 0;
        int ex = d;
        for (int o = 1; o < 32; o <<= 1) {
            int nb = __shfl_up_sync(0xffffffffu, ex, o);
            if (lane >= o) ex += nb;
        }
        int rowtot = __shfl_sync(0xffffffffu, ex, 31);
        ex -= d;                               // exclusive within row
        if (ok) g_rowptr[idx] = run + ex;
        run += rowtot;
    }
}

__global__ void fill_csr_kernel(const void* __restrict__ ei) {
    int e = blockIdx.x * blockDim.x + threadIdx.x;
    if (e >= E2) return;
    int s, d;
    if (e < N_EDGES) {
        s = fetch_idx(ei, e);
        d = fetch_idx(ei, (long long)N_EDGES + e);
    } else {
        s = e - N_EDGES; d = s;
    }
    int pos = g_rowptr[d] + atomicAdd(&g_fill[d], 1);
    g_cw[pos] = make_int2(s, __float_as_int(g_dinv[s] * g_dinv[d]));
}

// ---------------- SpMM (fp16 h): R9 winner form — warp per node, 8-deep MLP ----------------
template <bool STATS>
__global__ __launch_bounds__(256) void spmm_kernel(
    const __half* __restrict__ hin, __half* __restrict__ hout,
    const float* __restrict__ bias, const __half* __restrict__ h0p,
    float wacc, float wh0, int set)
{
    __shared__ float ss[STATS ? 8 : 1][STATS ? HID : 1];
    __shared__ float qq[STATS ? 8 : 1][STATS ? HID : 1];
    int warp = threadIdx.x >> 5;
    int node = blockIdx.x * 8 + warp;
    int lane = threadIdx.x & 31;
    const __half2* __restrict__ hin2 = (const __half2*)hin;
    const int4*    __restrict__ cw4  = (const int4*)g_cw;
    int beg = g_rowptr[node];
    int end = g_rowptr[node + 1];
    float2 a0 = make_float2(0.f, 0.f), a1 = a0, a2 = a0, a3 = a0;
    int e = beg;
    if ((e & 1) && e < end) {               // peel to 16B alignment of metadata
        int2 cw = g_cw[e];
        float w = __int_as_float(cw.y);
        float2 v = __half22float2(hin2[cw.x*32 + lane]);
        a0.x += w*v.x; a0.y += w*v.y;
        e++;
    }
    for (; e + 7 < end; e += 8) {
        int4 q0 = cw4[e >> 1];
        int4 q1 = cw4[(e >> 1) + 1];
        int4 q2 = cw4[(e >> 1) + 2];
        int4 q3 = cw4[(e >> 1) + 3];
        float2 v0 = __half22float2(hin2[q0.x*32 + lane]);
        float2 v1 = __half22float2(hin2[q0.z*32 + lane]);
        float2 v2 = __half22float2(hin2[q1.x*32 + lane]);
        float2 v3 = __half22float2(hin2[q1.z*32 + lane]);
        float2 v4 = __half22float2(hin2[q2.x*32 + lane]);
        float2 v5 = __half22float2(hin2[q2.z*32 + lane]);
        float2 v6 = __half22float2(hin2[q3.x*32 + lane]);
        float2 v7 = __half22float2(hin2[q3.z*32 + lane]);
        float w0 = __int_as_float(q0.y), w1 = __int_as_float(q0.w);
        float w2 = __int_as_float(q1.y), w3 = __int_as_float(q1.w);
        float w4 = __int_as_float(q2.y), w5 = __int_as_float(q2.w);
        float w6 = __int_as_float(q3.y), w7 = __int_as_float(q3.w);
        a0.x += w0*v0.x; a0.y += w0*v0.y;
        a1.x += w1*v1.x; a1.y += w1*v1.y;
        a2.x += w2*v2.x; a2.y += w2*v2.y;
        a3.x += w3*v3.x; a3.y += w3*v3.y;
        a0.x += w4*v4.x; a0.y += w4*v4.y;
        a1.x += w5*v5.x; a1.y += w5*v5.y;
        a2.x += w6*v6.x; a2.y += w6*v6.y;
        a3.x += w7*v7.x; a3.y += w7*v7.y;
    }
    for (; e + 1 < end; e += 2) {
        int4 q0 = cw4[e >> 1];
        float2 v0 = __half22float2(hin2[q0.x*32 + lane]);
        float2 v1 = __half22float2(hin2[q0.z*32 + lane]);
        float w0 = __int_as_float(q0.y), w1 = __int_as_float(q0.w);
        a0.x += w0*v0.x; a0.y += w0*v0.y;
        a1.x += w1*v1.x; a1.y += w1*v1.y;
    }
    if (e < end) {
        int2 cw = g_cw[e];
        float w = __int_as_float(cw.y);
        float2 v = __half22float2(hin2[cw.x*32 + lane]);
        a0.x += w*v.x; a0.y += w*v.y;
    }
    float2 r;
    r.x = ((a0.x + a1.x) + (a2.x + a3.x)) * wacc;
    r.y = ((a0.y + a1.y) + (a2.y + a3.y)) * wacc;
    if (bias) {
        float2 b = ((const float2*)bias)[lane];
        r.x += b.x; r.y += b.y;
    }
    if (h0p) {
        float2 z = __half22float2(((const __half2*)h0p)[node*32 + lane]);
        r.x += wh0 * z.x; r.y += wh0 * z.y;
    }
    ((__half2*)hout)[node*32 + lane] = __floats2half2_rn(r.x, r.y);
    if (STATS) {
        ss[warp][2*lane]     = r.x;
        ss[warp][2*lane + 1] = r.y;
        qq[warp][2*lane]     = r.x * r.x;
        qq[warp][2*lane + 1] = r.y * r.y;
        __syncthreads();
        int t = threadIdx.x;
        if (t < HID) {
            float s = 0.f;
#pragma unroll
            for (int g = 0; g < 8; g++) s += ss[g][t];
            atomicAdd(&g_sumf[set][t], s);
        } else if (t < 2 * HID) {
            float q = 0.f;
#pragma unroll
            for (int g = 0; g < 8; g++) q += qq[g][t - HID];
            atomicAdd(&g_sqf[set][t - HID], q);
        }
    }
}

// ---------------- tensor-core GEMM: block = 128 nodes x 64 features, wmma 16x16x16 ----------------
// C[N,64] = act(A)[N,KIN] @ W[KIN,64] (+bias); act = BN(scale,shift)+ReLU when BNSET>=0.
// A staged to smem fp16 (BN fused), W staged fp16; fp32 accumulate; epilogue via smem Cs.
template <int KIN, int BNSET, typename TA>
__global__ __launch_bounds__(256) void gemm_mma_kernel(
    const TA* __restrict__ A, const float* __restrict__ W,
    const float* __restrict__ bias, __half* __restrict__ C,
    const float* __restrict__ gam, const float* __restrict__ bet)
{
    struct Stage { __half As[128][72]; __half Ws[64][72]; };
    __shared__ union U { Stage st; float Cs[128][68]; U(){} } SM;
    __shared__ float sc[HID], sh[HID];
    int tid  = threadIdx.x;
    int warp = tid >> 5;
    if (BNSET >= 0) {
        if (tid < HID) {
            float mean = g_sumf[BNSET][tid] * INV_Nf;
            float var  = g_sqf[BNSET][tid] * INV_Nf - mean * mean;
            float s = gam[tid] * rsqrtf(var + BN_EPS);
            sc[tid] = s;
            sh[tid] = bet[tid] - mean * s;
        }
        __syncthreads();
    }
    int base = blockIdx.x * 128;
    wmma::fragment<wmma::accumulator, 16, 16, 16, float> acc[4];
#pragma unroll
    for (int i = 0; i < 4; i++) wmma::fill_fragment(acc[i], 0.f);

    for (int k0 = 0; k0 < KIN; k0 += 64) {
        __syncthreads();
        // stage A chunk: 128 rows x 64 k (pairs), BN+ReLU fused, fp16 out
        for (int i = tid; i < 128 * 32; i += 256) {
            int r = i >> 5, c = (i & 31) * 2;
            float v0 = 0.f, v1 = 0.f;
            if (base + r < N_NODES) {
                if constexpr (sizeof(TA) == 2) {
                    float2 p = __half22float2(((const __half2*)A)[((base + r) * KIN + k0 + c) >> 1]);
                    v0 = p.x; v1 = p.y;
                } else {
                    float2 p = ((const float2*)A)[((base + r) * KIN + k0 + c) >> 1];
                    v0 = p.x; v1 = p.y;
                }
            }
            if (BNSET >= 0) {
                v0 = fmaxf(fmaf(v0, sc[k0 + c],     sh[k0 + c]),     0.f);
                v1 = fmaxf(fmaf(v1, sc[k0 + c + 1], sh[k0 + c + 1]), 0.f);
            }
            *reinterpret_cast<__half2*>(&SM.st.As[r][c]) = __floats2half2_rn(v0, v1);
        }
        // stage W chunk: 64 k x 64 n, fp16
        for (int i = tid; i < 64 * 32; i += 256) {
            int k = i >> 5, n = (i & 31) * 2;
            float2 p = ((const float2*)W)[((k0 + k) * 64 + n) >> 1];
            *reinterpret_cast<__half2*>(&SM.st.Ws[k][n]) = __floats2half2_rn(p.x, p.y);
        }
        __syncthreads();
        int r0 = warp * 16;
#pragma unroll
        for (int kk = 0; kk < 64; kk += 16) {
            wmma::fragment<wmma::matrix_a, 16, 16, 16, __half, wmma::row_major> af;
            wmma::load_matrix_sync(af, &SM.st.As[r0][kk], 72);
#pragma unroll
            for (int nt = 0; nt < 4; nt++) {
                wmma::fragment<wmma::matrix_b, 16, 16, 16, __half, wmma::row_major> bf;
                wmma::load_matrix_sync(bf, &SM.st.Ws[kk][nt * 16], 72);
                wmma::mma_sync(acc[nt], af, bf, acc[nt]);
            }
        }
    }
    __syncthreads();   // As/Ws dead; Cs aliases them
#pragma unroll
    for (int nt = 0; nt < 4; nt++)
        wmma::store_matrix_sync(&SM.Cs[warp * 16][nt * 16], acc[nt], 68, wmma::mem_row_major);
    __syncthreads();
    // epilogue: bias + fp16 convert + coalesced store
    for (int i = tid; i < 128 * 32; i += 256) {
        int r = i >> 5, c = (i & 31) * 2;
        int node = base + r;
        if (node < N_NODES) {
            float b0 = bias ? bias[c]     : 0.f;
            float b1 = bias ? bias[c + 1] : 0.f;
            ((__half2*)C)[(node * 64 + c) >> 1] =
                __floats2half2_rn(SM.Cs[r][c] + b0, SM.Cs[r][c + 1] + b1);
        }
    }
}

// ---------------- layer-4 BN apply (inline finalize) -> writes h and h0 (fp16) ----------------
__global__ __launch_bounds__(256) void bn_apply_final_kernel(
    __half* __restrict__ h, __half* __restrict__ h0,
    const float* __restrict__ gam, const float* __restrict__ bet)
{
    __shared__ float sc[HID], sh[HID];
    int tid = threadIdx.x;
    if (tid < HID) {
        float mean = g_sumf[3][tid] * INV_Nf;
        float var  = g_sqf[3][tid] * INV_Nf - mean * mean;
        float s = gam[tid] * rsqrtf(var + BN_EPS);
        sc[tid] = s;
        sh[tid] = bet[tid] - mean * s;
    }
    __syncthreads();
    int i = blockIdx.x * blockDim.x + tid;   // over N*32 half2s (exact)
    float2 v = __half22float2(((const __half2*)h)[i]);
    int f = (i * 2) & (HID - 1);
    v.x = fmaxf(fmaf(v.x, sc[f],     sh[f]),     0.f);
    v.y = fmaxf(fmaf(v.y, sc[f + 1], sh[f + 1]), 0.f);
    __half2 o = __floats2half2_rn(v.x, v.y);
    ((__half2*)h)[i]  = o;
    ((__half2*)h0)[i] = o;
}

// ---------------- fused FC + log-softmax: out = log_softmax(A @ Wfc + bfc) ----------------
__global__ __launch_bounds__(256) void fc_logsoftmax_kernel(
    const __half* __restrict__ A, const float* __restrict__ W,
    const float* __restrict__ bias, float* __restrict__ out)
{
    __shared__ float Ws[64 * 64];
    __shared__ float As[32 * 64];
    __shared__ float L[32][65];
    int tid = threadIdx.x;
    for (int i = tid; i < 64 * 64; i += 256) Ws[i] = W[i];
    int base = blockIdx.x * 32;
    for (int i = tid; i < 32 * 32; i += 256) {     // 32 rows x 32 half2
        int r = i / 32, c = (i - r * 32) * 2;
        float2 p = make_float2(0.f, 0.f);
        if (base + r < N_NODES)
            p = __half22float2(((const __half2*)A)[((base + r) * 64 + c) >> 1]);
        As[r * 64 + c]     = p.x;
        As[r * 64 + c + 1] = p.y;
    }
    __syncthreads();
    int f  = tid & 63;
    int ig = tid >> 6;
    float acc[8];
#pragma unroll
    for (int i = 0; i < 8; i++) acc[i] = 0.f;
#pragma unroll 8
    for (int k = 0; k < 64; k++) {
        float wv = Ws[k * 64 + f];
#pragma unroll
        for (int i = 0; i < 8; i++)
            acc[i] += As[(ig * 8 + i) * 64 + k] * wv;
    }
    float bv = bias[f];
#pragma unroll
    for (int i = 0; i < 8; i++) L[ig * 8 + i][f] = acc[i] + bv;
    __syncthreads();
    int w = tid >> 5, lane = tid & 31;
#pragma unroll
    for (int j = 0; j < 4; j++) {
        int r = w * 4 + j;
        int node = base + r;
        if (node >= N_NODES) break;
        float v0 = L[r][lane], v1 = L[r][lane + 32];
        float m = fmaxf(v0, v1);
        for (int o = 16; o; o >>= 1) m = fmaxf(m, __shfl_xor_sync(0xffffffffu, m, o));
        float s = __expf(v0 - m) + __expf(v1 - m);
        for (int o = 16; o; o >>= 1) s += __shfl_xor_sync(0xffffffffu, s, o);
        float ls = m + __logf(s);
        out[node * 64 + lane]      = v0 - ls;
        out[node * 64 + lane + 32] = v1 - ls;
    }
}

// ---------------- host ----------------
extern "C" void kernel_launch(void* const* d_in, const int* in_sizes, int n_in,
                              void* d_out, int out_size) {
    const float* x   = (const float*)d_in[0];
    const void*  ei  = d_in[1];            // int32 or int64, detected on device
    const float* W1  = (const float*)d_in[2];
    const float* b1  = (const float*)d_in[3];
    const float* W2  = (const float*)d_in[4];
    const float* b2  = (const float*)d_in[5];
    const float* Wx  = (const float*)d_in[6];   // [2,64,64]
    const float* bx  = (const float*)d_in[7];   // [2,64]
    const float* g1  = (const float*)d_in[8];
    const float* be1 = (const float*)d_in[9];
    const float* g2  = (const float*)d_in[10];
    const float* be2 = (const float*)d_in[11];
    const float* g3  = (const float*)d_in[12];
    const float* be3 = (const float*)d_in[13];
    const float* Wfc = (const float*)d_in[14];
    const float* bfc = (const float*)d_in[15];
    float* out = (float*)d_out;

    __half *hA, *hB, *h0;
    cudaGetSymbolAddress((void**)&hA, g_hA);
    cudaGetSymbolAddress((void**)&hB, g_hB);
    cudaGetSymbolAddress((void**)&h0, g_h0);

    // ---- build normalized CSR (by dst) ----
    init_kernel<<<(N_NODES + 255) / 256, 256>>>((const int*)ei);
    count_deg_kernel<<<(N_EDGES + 255) / 256, 256>>>(ei);
    scan_kernel<<<1, 1024>>>();
    fill_csr_kernel<<<(E2 + 255) / 256, 256>>>(ei);

    const int GEMM_GRID = (N_NODES + 127) / 128;   // 391
    const int FC_GRID   = (N_NODES + 31) / 32;     // 1563
    const int SPMM_GRID = N_NODES / 8;             // 6250

    // ---- layer 1 (IN_F=128 fp32 input, no BN) ----
    gemm_mma_kernel<128, -1, float><<<GEMM_GRID, 256>>>(x, W1, nullptr, hB, nullptr, nullptr);
    spmm_kernel<true><<<SPMM_GRID, 256>>>(hB, hA, b1, nullptr, 1.f, 0.f, 0);
    // ---- layer 2 (BN set 0 fused into GEMM input) ----
    gemm_mma_kernel<64, 0, __half><<<GEMM_GRID, 256>>>(hA, W2, nullptr, hB, g1, be1);
    spmm_kernel<true><<<SPMM_GRID, 256>>>(hB, hA, b2, nullptr, 1.f, 0.f, 1);
    // ---- extra layer 0 (BN set 1) ----
    gemm_mma_kernel<64, 1, __half><<<GEMM_GRID, 256>>>(hA, Wx, nullptr, hB, g2, be2);
    spmm_kernel<true><<<SPMM_GRID, 256>>>(hB, hA, bx, nullptr, 1.f, 0.f, 2);
    // ---- extra layer 1 (BN set 2) ----
    gemm_mma_kernel<64, 2, __half><<<GEMM_GRID, 256>>>(hA, Wx + 64 * 64, nullptr, hB, g3, be3);
    spmm_kernel<true><<<SPMM_GRID, 256>>>(hB, hA, bx + 64, nullptr, 1.f, 0.f, 3);
    // ---- final BN apply (set 3) -> hA normalized, h0 copy ----
    bn_apply_final_kernel<<<(N_NODES * 32) / 256, 256>>>(hA, h0, g3, be3);

    // ---- APPNP: 10 steps, ping-pong hA <-> hB ----
    __half* cur = hA;
    __half* nxt = hB;
    for (int it = 0; it < 10; it++) {
        spmm_kernel<false><<<SPMM_GRID, 256>>>(cur, nxt, nullptr, h0, 0.9f, 0.1f, 0);
        __half* t = cur; cur = nxt; nxt = t;
    }
    // result in hA

    // ---- head: FC + log_softmax fused ----
    fc_logsoftmax_kernel<<<FC_GRID, 256>>>(cur, Wfc, bfc, out);
}